// round 12
// baseline (speedup 1.0000x reference)
#include <cuda_runtime.h>
#include <math.h>

// Problem shape (fixed per reference): h is (32, 4096, 1024) fp32.
#define BATCH   32
#define SEQ     4096
#define HID     1024
#define W       32          // window rows
#define WSTART  2032        // 4096/2 - 16
#define NCH     8           // d-chunks
#define CHUNK   128         // HID / NCH
#define NPAIR   528         // 32*33/2 upper-triangle incl diag
#define FULLM   0xFFFFFFFFu

// Scratch: per-batch, per-chunk partial Gram (upper triangle), fp32.
__device__ float g_part[BATCH][NCH][NPAIR];

// ---------------------------------------------------------------------------
// Kernel 1: partial raw Gram R = W W^T over a 128-column chunk.
// grid = (NCH, BATCH), block = 544.  (proven)
// ---------------------------------------------------------------------------
__global__ void __launch_bounds__(544) gram_kernel(const float* __restrict__ h) {
    const int chunk = blockIdx.x;
    const int b     = blockIdx.y;
    __shared__ float As[W][CHUNK + 1];

    const int tid = threadIdx.x;
    const float* base = h + ((size_t)b * SEQ + WSTART) * HID + (size_t)chunk * CHUNK;

    for (int idx = tid; idx < W * (CHUNK / 4); idx += blockDim.x) {
        int row = idx >> 5;
        int c4  = idx & 31;
        float4 v = *(const float4*)(base + (size_t)row * HID + c4 * 4);
        As[row][c4 * 4 + 0] = v.x;
        As[row][c4 * 4 + 1] = v.y;
        As[row][c4 * 4 + 2] = v.z;
        As[row][c4 * 4 + 3] = v.w;
    }
    __syncthreads();

    if (tid < NPAIR) {
        int i = 0, rem = tid;
        while (rem >= W - i) { rem -= W - i; i++; }
        int j = i + rem;

        const float* ai = As[i];
        const float* aj = As[j];
        float a0 = 0.f, a1 = 0.f, a2 = 0.f, a3 = 0.f;
        #pragma unroll
        for (int d = 0; d < CHUNK; d += 4) {
            a0 = fmaf(ai[d + 0], aj[d + 0], a0);
            a1 = fmaf(ai[d + 1], aj[d + 1], a1);
            a2 = fmaf(ai[d + 2], aj[d + 2], a2);
            a3 = fmaf(ai[d + 3], aj[d + 3], a3);
        }
        g_part[b][chunk][tid] = (a0 + a1) + (a2 + a3);
    }
}

// ---------------------------------------------------------------------------
// Helpers
// ---------------------------------------------------------------------------
__device__ __forceinline__ float wmin32(float v) {
    #pragma unroll
    for (int o = 16; o; o >>= 1) v = fminf(v, __shfl_xor_sync(FULLM, v, o));
    return v;
}
__device__ __forceinline__ float wmax32(float v) {
    #pragma unroll
    for (int o = 16; o; o >>= 1) v = fmaxf(v, __shfl_xor_sync(FULLM, v, o));
    return v;
}

// Dynamic select a[k] (runtime k) from a static register array (used once).
__device__ __forceinline__ float sel32(const float (&a)[32], int k) {
    float t16[16], t8[8], t4[4], t2[2];
    #pragma unroll
    for (int j = 0; j < 16; j++) t16[j] = (k & 16) ? a[j + 16] : a[j];
    #pragma unroll
    for (int j = 0; j < 8;  j++) t8[j]  = (k & 8)  ? t16[j + 8] : t16[j];
    #pragma unroll
    for (int j = 0; j < 4;  j++) t4[j]  = (k & 4)  ? t8[j + 4]  : t8[j];
    #pragma unroll
    for (int j = 0; j < 2;  j++) t2[j]  = (k & 2)  ? t4[j + 2]  : t4[j];
    return (k & 1) ? t2[1] : t2[0];
}

// Sturm count for 32x32 tridiagonal: #eigs < x.
__device__ __forceinline__ int sturm32(const float* __restrict__ dS,
                                       const float* __restrict__ e2S, float x) {
    float dp = dS[0] - x;
    int cnt = (dp < 0.f) ? 1 : 0;
    #pragma unroll
    for (int i = 1; i < 32; i++) {
        float den = copysignf(fmaxf(fabsf(dp), 1e-25f), dp);
        dp = (dS[i] - x) - __fdividef(e2S[i - 1], den);
        cnt += (dp < 0.f) ? 1 : 0;
    }
    return cnt;
}

// ---------------------------------------------------------------------------
// Kernel 2: per-batch. FP32 prologue (256 threads). Warp 0: FULLY-UNROLLED
// Householder tridiagonalization — k compile-time, so each lane's column-k
// element is a STATIC register a[k]: parallel 1-STS publish, no divergent
// lane-k section, no sel32, 2 syncwarps/step. Then multi-point Sturm.
// ---------------------------------------------------------------------------
__global__ void __launch_bounds__(256) eig_kernel(float* __restrict__ out, int n) {
    const int b = blockIdx.x;
    if (b >= BATCH) return;
    const int tid  = threadIdx.x;
    const int lane = tid & 31;
    const int wid  = tid >> 5;

    __shared__ float  Gs[W][W + 1];
    __shared__ float  rsum[W];
    __shared__ float  Ssum;
    __shared__ float  traceSh;
    __shared__ float  dinv[W];
    __shared__ float  Abuf[W][W + 1];
    __shared__ __align__(16) float xSh[W];   // x / v vector
    __shared__ __align__(16) float pSh[W];   // p vector
    __shared__ float  dS[W];
    __shared__ float  e2S[W];
    __shared__ float  eaS[W];

    // --- reduce chunk partials (fp32), mirror to full symmetric matrix ---
    for (int t = tid; t < NPAIR; t += 256) {
        float g = 0.f;
        #pragma unroll
        for (int c = 0; c < NCH; c++) g += g_part[b][c][t];
        int i = 0, rem = t;
        while (rem >= W - i) { rem -= W - i; i++; }
        int j = i + rem;
        Gs[i][j] = g;
        Gs[j][i] = g;
    }
    __syncthreads();

    if (tid < W) {
        float r0 = 0.f, r1 = 0.f, r2 = 0.f, r3 = 0.f;
        #pragma unroll
        for (int j = 0; j < W; j += 4) {
            r0 += Gs[tid][j + 0]; r1 += Gs[tid][j + 1];
            r2 += Gs[tid][j + 2]; r3 += Gs[tid][j + 3];
        }
        rsum[tid] = (r0 + r1) + (r2 + r3);
    }
    __syncthreads();
    if (tid == 0) {
        float s0 = 0.f, s1 = 0.f, s2 = 0.f, s3 = 0.f;
        #pragma unroll
        for (int i = 0; i < W; i += 4) {
            s0 += rsum[i + 0]; s1 += rsum[i + 1];
            s2 += rsum[i + 2]; s3 += rsum[i + 3];
        }
        Ssum = (s0 + s1) + (s2 + s3);
    }
    __syncthreads();

    const float Sq = Ssum * (1.0f / 1024.0f);   // S / 32^2

    if (tid < W) {
        float di = Gs[tid][tid] - rsum[tid] * (1.0f / 16.0f) + Sq;
        if (di < 0.f) di = 0.f;
        dinv[tid] = __fdividef(1.f, sqrtf(di) + 1e-8f);
    }
    __syncthreads();

    #pragma unroll
    for (int e = 0; e < 4; e++) {
        int idx = tid + e * 256;
        int k = idx >> 5, l = idx & 31;
        float gc = Gs[k][l] - (rsum[k] + rsum[l]) * (1.0f / 32.0f) + Sq;
        Abuf[k][l] = gc * dinv[k] * dinv[l];
    }
    __syncthreads();
    if (tid == 0) {
        float t0 = 0.f, t1 = 0.f, t2 = 0.f, t3 = 0.f;
        #pragma unroll
        for (int i = 0; i < W; i += 4) {
            t0 += Abuf[i + 0][i + 0]; t1 += Abuf[i + 1][i + 1];
            t2 += Abuf[i + 2][i + 2]; t3 += Abuf[i + 3][i + 3];
        }
        traceSh = (t0 + t1) + (t2 + t3);
    }
    __syncthreads();

    if (wid != 0) return;   // warps 1..7 retire; warp 0 owns the eigensolve

    // ================= Householder tridiagonalization (fully unrolled) ======
    // Lane i holds row i in registers a[0..31]. With k compile-time:
    //   column-k element of lane i = a[k]  (static register index).
    float a[32];
    #pragma unroll
    for (int j = 0; j < 32; j++) a[j] = Abuf[lane][j];

    const float4* x4 = reinterpret_cast<const float4*>(xSh);
    const float4* p4 = reinterpret_cast<const float4*>(pSh);

    #pragma unroll
    for (int k = 0; k < 30; k++) {
        const int m = k + 1;

        // 1) ALL lanes publish their masked column-k element (no divergence).
        xSh[lane] = (lane > k) ? a[k] : 0.f;
        __syncwarp();

        // 2) Load x, compute sigma/alpha/beta redundantly (identical values).
        float xr[32];
        #pragma unroll
        for (int c = 0; c < 8; c++) {
            float4 v = x4[c];
            xr[4 * c + 0] = v.x; xr[4 * c + 1] = v.y;
            xr[4 * c + 2] = v.z; xr[4 * c + 3] = v.w;
        }
        float s0 = 0.f, s1 = 0.f, s2 = 0.f, s3 = 0.f;
        #pragma unroll
        for (int j = 0; j < 32; j += 4) {
            s0 = fmaf(xr[j + 0], xr[j + 0], s0);
            s1 = fmaf(xr[j + 1], xr[j + 1], s1);
            s2 = fmaf(xr[j + 2], xr[j + 2], s2);
            s3 = fmaf(xr[j + 3], xr[j + 3], s3);
        }
        float sig = (s0 + s1) + (s2 + s3);
        float x0  = xr[m];                       // static index
        float nrm = sqrtf(sig);
        float alpha = -copysignf(nrm, x0);
        float beta  = (sig > 1e-30f) ? __fdividef(1.f, sig + fabsf(x0) * nrm) : 0.f;
        xr[m] = x0 - alpha;                      // patch v_m in registers

        // 3) p = beta * (A v); lanes < m hold stale rows -> mask.
        float q0 = 0.f, q1 = 0.f, q2 = 0.f, q3 = 0.f;
        #pragma unroll
        for (int j = 0; j < 32; j += 4) {
            q0 = fmaf(a[j + 0], xr[j + 0], q0);
            q1 = fmaf(a[j + 1], xr[j + 1], q1);
            q2 = fmaf(a[j + 2], xr[j + 2], q2);
            q3 = fmaf(a[j + 3], xr[j + 3], q3);
        }
        float p = ((q0 + q1) + (q2 + q3));
        p = (lane >= m) ? p * beta : 0.f;
        pSh[lane] = p;
        __syncwarp();

        // 4) vtp redundantly; rank-2 update all in registers.
        float pr[32];
        #pragma unroll
        for (int c = 0; c < 8; c++) {
            float4 v = p4[c];
            pr[4 * c + 0] = v.x; pr[4 * c + 1] = v.y;
            pr[4 * c + 2] = v.z; pr[4 * c + 3] = v.w;
        }
        float t0 = 0.f, t1 = 0.f, t2 = 0.f, t3 = 0.f;
        #pragma unroll
        for (int j = 0; j < 32; j += 4) {
            t0 = fmaf(xr[j + 0], pr[j + 0], t0);
            t1 = fmaf(xr[j + 1], pr[j + 1], t1);
            t2 = fmaf(xr[j + 2], pr[j + 2], t2);
            t3 = fmaf(xr[j + 3], pr[j + 3], t3);
        }
        float vtp = (t0 + t1) + (t2 + t3);
        float Kc  = 0.5f * beta * vtp;
        float vi  = (lane > k) ? ((lane == m) ? xr[m] : a[k]) : 0.f;
        float qi  = p - Kc * vi;                 // 0 for lanes < m

        #pragma unroll
        for (int j = 0; j < 32; j++) {
            float qj = fmaf(-Kc, xr[j], pr[j]);
            a[j] = fmaf(-vi, qj, fmaf(-qi, xr[j], a[j]));
        }

        if (lane == 0) { e2S[k] = alpha * alpha; eaS[k] = fabsf(alpha); }
        // no end-of-step sync needed: next step's xSh STS is ordered after
        // this step's pSh syncwarp; all xSh reads happened before it.
    }
    {   // last offdiagonal e_30 = A[30][31]
        float e30 = __shfl_sync(FULLM, a[31], 30);
        if (lane == 0) {
            e2S[30] = e30 * e30; eaS[30] = fabsf(e30);
            e2S[31] = 0.f;       eaS[31] = 0.f;
        }
    }
    dS[lane] = sel32(a, lane);   // diagonal (runtime index, once)
    __syncwarp();

    // ================= multi-point Sturm bisection ==========================
    float eprev = (lane > 0) ? eaS[lane - 1] : 0.f;
    float rad   = eaS[lane] + eprev;
    float lo = wmin32(dS[lane] - rad);
    float hi = wmax32(dS[lane] + rad);

    // 3 targets x 10 lanes: ascending eigen indices 31 (e0), 24 (e7), 23 (e8).
    int g = lane / 10; if (g > 2) g = 2;
    const int mm = lane - g * 10;                // 0..9 (lanes 30,31 ignored)
    const int idx = (g == 0) ? 31 : (g == 1) ? 24 : 23;

    #pragma unroll 1
    for (int r = 0; r < 8; r++) {
        float w  = (hi - lo) * (1.0f / 11.0f);
        float xx = lo + w * (float)(mm + 1);
        int   cnt  = sturm32(dS, e2S, xx);
        unsigned bal = __ballot_sync(FULLM, cnt <= idx);
        unsigned gb  = (bal >> (g * 10)) & 0x3FFu;
        int mstar = 31 - __clz(gb);              // -1..9
        lo = lo + w * (float)(mstar + 1);
        hi = lo + w;
    }
    float lam = 0.5f * (lo + hi);
    float e0 = __shfl_sync(FULLM, lam, 0);
    float e7 = __shfl_sync(FULLM, lam, 10);
    float e8 = __shfl_sync(FULLM, lam, 20);

    if (lane == 0) {
        float gap   = e7 - e8;
        float decay = (e0 - e8) * (1.0f / 9.0f);
        float lmin  = e8 + 1e-8f;
        float topo  = gap / (decay + 1e-8f);
        if (topo < 0.f) topo = 0.f;
        float geo   = lmin / (traceSh + 1e-8f);
        float gcve  = topo + geo;
        out[b]         = gcve;   // gcve_scores
        out[n + b]     = 0.0f;   // fracture_scores
        out[2 * n + b] = gcve;   // total_pressure
    }
}

// ---------------------------------------------------------------------------
extern "C" void kernel_launch(void* const* d_in, const int* in_sizes, int n_in,
                              void* d_out, int out_size) {
    const float* h = (const float*)d_in[0];
    float* out = (float*)d_out;
    int n = out_size / 3;   // 32

    dim3 g1(NCH, BATCH);
    gram_kernel<<<g1, 544>>>(h);
    eig_kernel<<<148, 256>>>(out, n);   // blocks >= 32 exit immediately
}

// round 16
// speedup vs baseline: 1.3808x; 1.3808x over previous
#include <cuda_runtime.h>
#include <math.h>

// Problem shape (fixed per reference): h is (32, 4096, 1024) fp32.
#define BATCH   32
#define SEQ     4096
#define HID     1024
#define W       32          // window rows
#define WSTART  2032        // 4096/2 - 16
#define NCH     8           // d-chunks
#define CHUNK   128         // HID / NCH
#define NPAIR   528         // 32*33/2 upper-triangle incl diag
#define FULLM   0xFFFFFFFFu

// Scratch: per-batch, per-chunk partial Gram (upper triangle), fp32.
__device__ float g_part[BATCH][NCH][NPAIR];

// ---------------------------------------------------------------------------
// Kernel 1: partial raw Gram R = W W^T over a 128-column chunk.
// grid = (NCH, BATCH), block = 544.  (proven)
// ---------------------------------------------------------------------------
__global__ void __launch_bounds__(544) gram_kernel(const float* __restrict__ h) {
    const int chunk = blockIdx.x;
    const int b     = blockIdx.y;
    __shared__ float As[W][CHUNK + 1];

    const int tid = threadIdx.x;
    const float* base = h + ((size_t)b * SEQ + WSTART) * HID + (size_t)chunk * CHUNK;

    for (int idx = tid; idx < W * (CHUNK / 4); idx += blockDim.x) {
        int row = idx >> 5;
        int c4  = idx & 31;
        float4 v = *(const float4*)(base + (size_t)row * HID + c4 * 4);
        As[row][c4 * 4 + 0] = v.x;
        As[row][c4 * 4 + 1] = v.y;
        As[row][c4 * 4 + 2] = v.z;
        As[row][c4 * 4 + 3] = v.w;
    }
    __syncthreads();

    if (tid < NPAIR) {
        int i = 0, rem = tid;
        while (rem >= W - i) { rem -= W - i; i++; }
        int j = i + rem;

        const float* ai = As[i];
        const float* aj = As[j];
        float a0 = 0.f, a1 = 0.f, a2 = 0.f, a3 = 0.f;
        #pragma unroll
        for (int d = 0; d < CHUNK; d += 4) {
            a0 = fmaf(ai[d + 0], aj[d + 0], a0);
            a1 = fmaf(ai[d + 1], aj[d + 1], a1);
            a2 = fmaf(ai[d + 2], aj[d + 2], a2);
            a3 = fmaf(ai[d + 3], aj[d + 3], a3);
        }
        g_part[b][chunk][tid] = (a0 + a1) + (a2 + a3);
    }
}

// ---------------------------------------------------------------------------
// Helpers
// ---------------------------------------------------------------------------
__device__ __forceinline__ float wsum32(float v) {
    #pragma unroll
    for (int o = 16; o; o >>= 1) v += __shfl_xor_sync(FULLM, v, o);
    return v;
}
__device__ __forceinline__ float wmin32(float v) {
    #pragma unroll
    for (int o = 16; o; o >>= 1) v = fminf(v, __shfl_xor_sync(FULLM, v, o));
    return v;
}
__device__ __forceinline__ float wmax32(float v) {
    #pragma unroll
    for (int o = 16; o; o >>= 1) v = fmaxf(v, __shfl_xor_sync(FULLM, v, o));
    return v;
}

// Dynamic select a[k] (runtime k) from a static register array: SEL mux tree.
__device__ __forceinline__ float sel32(const float (&a)[32], int k) {
    float t16[16], t8[8], t4[4], t2[2];
    #pragma unroll
    for (int j = 0; j < 16; j++) t16[j] = (k & 16) ? a[j + 16] : a[j];
    #pragma unroll
    for (int j = 0; j < 8;  j++) t8[j]  = (k & 8)  ? t16[j + 8] : t16[j];
    #pragma unroll
    for (int j = 0; j < 4;  j++) t4[j]  = (k & 4)  ? t8[j + 4]  : t8[j];
    #pragma unroll
    for (int j = 0; j < 2;  j++) t2[j]  = (k & 2)  ? t4[j + 2]  : t4[j];
    return (k & 1) ? t2[1] : t2[0];
}

// Sturm count via scaled characteristic-polynomial recurrence (division-free):
//   q_i = (c*d_i - c*x) * q_{i-1} - c^2 e2_{i-1} * q_{i-2}
// #eigs < x = #sign changes in (q_0=1, q_1, ..., q_32). c=1/16 bounds growth;
// periodic rescale guards underflow. Chain = 1 FMA per iteration.
__device__ __forceinline__ int sturm32(const float* __restrict__ dS,
                                       const float* __restrict__ e2S, float x) {
    const float c  = 0.0625f;            // 1/16
    const float c2 = 0.00390625f;        // 1/256
    const float cx = c * x;
    float qpp = 1.f;                     // q_0
    float qp  = fmaf(c, dS[0], -cx);     // q_1
    int cnt = (qp < 0.f) ? 1 : 0;
    #pragma unroll
    for (int j = 1; j < 32; j++) {
        float cd = fmaf(c, dS[j], -cx);
        float t  = (c2 * e2S[j - 1]) * qpp;     // off the critical chain
        float qn = fmaf(cd, qp, -t);
        cnt += ((qn < 0.f) != (qp < 0.f));
        qpp = qp; qp = qn;
        if ((j & 7) == 7) {                      // guard under/overflow
            float mag = fmaxf(fabsf(qp), fabsf(qpp));
            if (mag > 1e18f)      { qp *= 0x1p-60f; qpp *= 0x1p-60f; }
            else if (mag < 1e-18f){ qp *= 0x1p60f;  qpp *= 0x1p60f;  }
        }
    }
    return cnt;
}

// ---------------------------------------------------------------------------
// Kernel 2: per-batch. FP32 prologue (544 threads). Warp 0: Householder
// tridiag (rolled loop; parallel sel32 publish, double-buffered x, butterfly
// vtp, 2-FMA update) + division-free multi-point Sturm bisection.
// ---------------------------------------------------------------------------
__global__ void __launch_bounds__(544) eig_kernel(float* __restrict__ out, int n) {
    const int b = blockIdx.x;
    if (b >= BATCH) return;
    const int tid  = threadIdx.x;
    const int lane = tid & 31;
    const int wid  = tid >> 5;

    __shared__ float  Gs[W][W + 1];
    __shared__ float  rsum[W];
    __shared__ float  Ssum;
    __shared__ float  traceSh;
    __shared__ float  dinv[W];
    __shared__ float  Abuf[W][W + 1];
    __shared__ __align__(16) float xSh[2 * W];   // double-buffered x/v vector
    __shared__ __align__(16) float pSh[W];       // p vector
    __shared__ float  dS[W];
    __shared__ float  e2S[W];
    __shared__ float  eaS[W];

    // --- reduce chunk partials (fp32), mirror to full symmetric matrix ---
    if (tid < NPAIR) {
        float g = 0.f;
        #pragma unroll
        for (int c = 0; c < NCH; c++) g += g_part[b][c][tid];
        int i = 0, rem = tid;
        while (rem >= W - i) { rem -= W - i; i++; }
        int j = i + rem;
        Gs[i][j] = g;
        Gs[j][i] = g;
    }
    __syncthreads();

    if (tid < W) {
        float r0 = 0.f, r1 = 0.f, r2 = 0.f, r3 = 0.f;
        #pragma unroll
        for (int j = 0; j < W; j += 4) {
            r0 += Gs[tid][j + 0]; r1 += Gs[tid][j + 1];
            r2 += Gs[tid][j + 2]; r3 += Gs[tid][j + 3];
        }
        rsum[tid] = (r0 + r1) + (r2 + r3);
    }
    __syncthreads();
    if (tid == 0) {
        float s0 = 0.f, s1 = 0.f, s2 = 0.f, s3 = 0.f;
        #pragma unroll
        for (int i = 0; i < W; i += 4) {
            s0 += rsum[i + 0]; s1 += rsum[i + 1];
            s2 += rsum[i + 2]; s3 += rsum[i + 3];
        }
        Ssum = (s0 + s1) + (s2 + s3);
    }
    __syncthreads();

    const float Sq = Ssum * (1.0f / 1024.0f);   // S / 32^2

    if (tid < W) {
        float di = Gs[tid][tid] - rsum[tid] * (1.0f / 16.0f) + Sq;
        if (di < 0.f) di = 0.f;
        dinv[tid] = __fdividef(1.f, sqrtf(di) + 1e-8f);
    }
    __syncthreads();

    #pragma unroll
    for (int e = 0; e < 2; e++) {
        int idx = tid + e * 544;
        if (idx < W * W) {
            int k = idx >> 5, l = idx & 31;
            float gc = Gs[k][l] - (rsum[k] + rsum[l]) * (1.0f / 32.0f) + Sq;
            Abuf[k][l] = gc * dinv[k] * dinv[l];
        }
    }
    __syncthreads();
    if (tid == 0) {
        float t0 = 0.f, t1 = 0.f, t2 = 0.f, t3 = 0.f;
        #pragma unroll
        for (int i = 0; i < W; i += 4) {
            t0 += Abuf[i + 0][i + 0]; t1 += Abuf[i + 1][i + 1];
            t2 += Abuf[i + 2][i + 2]; t3 += Abuf[i + 3][i + 3];
        }
        traceSh = (t0 + t1) + (t2 + t3);
    }
    __syncthreads();

    if (wid != 0) return;   // warps 1..16 retire; warp 0 owns the eigensolve

    // ================= Householder tridiagonalization (rolled) ==============
    // Lane i holds row i in registers a[0..31]. Per step:
    //  R0: ALL lanes publish masked column element via sel32 (no divergence)
    //  R1: redundant sigma/alpha/beta from smem
    //  R2: lane m patches v_m
    //  R3: p = beta*(A v), publish p
    //  R4: vtp via shfl butterfly; 2-FMA rank-2 update
    float a[32];
    #pragma unroll
    for (int j = 0; j < 32; j++) a[j] = Abuf[lane][j];

    #pragma unroll 1
    for (int k = 0; k < 30; k++) {
        const int m = k + 1;
        float* xcur = xSh + ((k & 1) << 5);
        const float4* xc4 = reinterpret_cast<const float4*>(xcur);
        const float4* p4  = reinterpret_cast<const float4*>(pSh);

        // R0: parallel publish of masked column k
        float myx = sel32(a, k);
        myx = (lane > k) ? myx : 0.f;
        xcur[lane] = myx;
        __syncwarp();

        // R1: sigma/alpha/beta (redundant, identical across lanes)
        float s0 = 0.f, s1 = 0.f, s2 = 0.f, s3 = 0.f;
        #pragma unroll
        for (int c = 0; c < 8; c++) {
            float4 v = xc4[c];
            s0 = fmaf(v.x, v.x, s0); s1 = fmaf(v.y, v.y, s1);
            s2 = fmaf(v.z, v.z, s2); s3 = fmaf(v.w, v.w, s3);
        }
        float sig = (s0 + s1) + (s2 + s3);
        float x0  = xcur[m];
        float nrm = sqrtf(sig);
        float alpha = -copysignf(nrm, x0);
        float beta  = (sig > 1e-30f) ? __fdividef(1.f, sig + fabsf(x0) * nrm) : 0.f;
        if (lane == 0) { e2S[k] = alpha * alpha; eaS[k] = fabsf(alpha); }
        __syncwarp();

        // R2: patch v_m
        if (lane == m) xcur[m] = x0 - alpha;
        __syncwarp();

        // R3: p = beta * (A v); stale rows (lane < m) masked
        float q0 = 0.f, q1 = 0.f, q2 = 0.f, q3 = 0.f;
        #pragma unroll
        for (int c = 0; c < 8; c++) {
            float4 v = xc4[c];
            q0 = fmaf(a[4 * c + 0], v.x, q0);
            q1 = fmaf(a[4 * c + 1], v.y, q1);
            q2 = fmaf(a[4 * c + 2], v.z, q2);
            q3 = fmaf(a[4 * c + 3], v.w, q3);
        }
        float p = ((q0 + q1) + (q2 + q3));
        p = (lane >= m) ? p * beta : 0.f;
        pSh[lane] = p;
        __syncwarp();

        // R4: vtp via butterfly; 2-FMA update
        float vi  = (lane == m) ? (x0 - alpha) : myx;   // myx=0 for lane<=k
        float vtp = wsum32(vi * p);
        float Kc  = 0.5f * beta * vtp;
        float ui  = fmaf(-2.f * Kc, vi, p);             // ui = p - 2*Kc*vi

        #pragma unroll
        for (int c = 0; c < 8; c++) {
            float4 vv = xc4[c];
            float4 pp = p4[c];
            a[4 * c + 0] = fmaf(-vi, pp.x, fmaf(-ui, vv.x, a[4 * c + 0]));
            a[4 * c + 1] = fmaf(-vi, pp.y, fmaf(-ui, vv.y, a[4 * c + 1]));
            a[4 * c + 2] = fmaf(-vi, pp.z, fmaf(-ui, vv.z, a[4 * c + 2]));
            a[4 * c + 3] = fmaf(-vi, pp.w, fmaf(-ui, vv.w, a[4 * c + 3]));
        }
        // next step writes the OTHER x buffer; pSh next write is 3 syncs away
    }
    {   // last offdiagonal e_30 = A[30][31]
        float e30 = __shfl_sync(FULLM, a[31], 30);
        if (lane == 0) {
            e2S[30] = e30 * e30; eaS[30] = fabsf(e30);
            e2S[31] = 0.f;       eaS[31] = 0.f;
        }
    }
    dS[lane] = sel32(a, lane);   // diagonal (runtime index, once)
    __syncwarp();

    // ================= multi-point Sturm bisection ==========================
    float eprev = (lane > 0) ? eaS[lane - 1] : 0.f;
    float rad   = eaS[lane] + eprev;
    float lo = wmin32(dS[lane] - rad);
    float hi = wmax32(dS[lane] + rad);

    // 3 targets x 10 lanes: ascending eigen indices 31 (e0), 24 (e7), 23 (e8).
    int g = lane / 10; if (g > 2) g = 2;
    const int mm = lane - g * 10;                // 0..9 (lanes 30,31 ignored)
    const int idx = (g == 0) ? 31 : (g == 1) ? 24 : 23;

    #pragma unroll 1
    for (int r = 0; r < 8; r++) {
        float w  = (hi - lo) * (1.0f / 11.0f);
        float xx = lo + w * (float)(mm + 1);
        int   cnt  = sturm32(dS, e2S, xx);
        unsigned bal = __ballot_sync(FULLM, cnt <= idx);
        unsigned gb  = (bal >> (g * 10)) & 0x3FFu;
        int mstar = 31 - __clz(gb);              // -1..9
        lo = lo + w * (float)(mstar + 1);
        hi = lo + w;
    }
    float lam = 0.5f * (lo + hi);
    float e0 = __shfl_sync(FULLM, lam, 0);
    float e7 = __shfl_sync(FULLM, lam, 10);
    float e8 = __shfl_sync(FULLM, lam, 20);

    if (lane == 0) {
        float gap   = e7 - e8;
        float decay = (e0 - e8) * (1.0f / 9.0f);
        float lmin  = e8 + 1e-8f;
        float topo  = gap / (decay + 1e-8f);
        if (topo < 0.f) topo = 0.f;
        float geo   = lmin / (traceSh + 1e-8f);
        float gcve  = topo + geo;
        out[b]         = gcve;   // gcve_scores
        out[n + b]     = 0.0f;   // fracture_scores
        out[2 * n + b] = gcve;   // total_pressure
    }
}

// ---------------------------------------------------------------------------
extern "C" void kernel_launch(void* const* d_in, const int* in_sizes, int n_in,
                              void* d_out, int out_size) {
    const float* h = (const float*)d_in[0];
    float* out = (float*)d_out;
    int n = out_size / 3;   // 32

    dim3 g1(NCH, BATCH);
    gram_kernel<<<g1, 544>>>(h);
    eig_kernel<<<148, 544>>>(out, n);   // blocks >= 32 exit immediately
}